// round 16
// baseline (speedup 1.0000x reference)
#include <cuda_runtime.h>
#include <cuda_bf16.h>
#include <cstdint>
#include <cstddef>

// Problem constants
#define N_    32
#define C_    64
#define T_    1024
#define V_    25
#define K_    3
#define O_    192
#define EPSV  1e-5f

#define TPOS  4
#define NBLK1 (N_ * (T_ / TPOS))   // 8192
#define THREADS 256

// ---- smem layout (bytes) for k_gcn ----
#define XHI_B   0        // bf16 [104 pos][64 cin] SW128 rows (13312 B)
#define XLO_B   13312
#define Y_B     26624    // f32 [192][51] = 39168 B (odd stride: conflict-free cols)
#define AF_B    65792    // f32 [3][25][28] = 8400 B
#define PART_B  74192    // f32 [512] = 2048 B
#define SMEM_TOTAL 76240 // 3x = 228720 <= 227KB carveout -> 3 CTAs/SM

// k_out smem: f32 [200][65] = 52000 B -> 4 CTAs/SM
#define KOUT_SMEM 52000

// ---- device scratch ----
__device__ float    g_agg2[(size_t)N_ * T_ * V_ * C_];   // [n][t][v][c] (transposed!)
__device__ float    g_psum[NBLK1 * C_];
__device__ float    g_psumsq[NBLK1 * C_];
__device__ float    g_scale[C_];
__device__ float    g_shift[C_];
__device__ uint32_t g_wfrag[48 * 2 * 32 * 4];   // [mt*4+ks][hi/lo][lane][4 regs]
__device__ float    g_af[K_ * V_ * 28];         // padded, pads zeroed
__device__ float    g_beff[C_ * V_];            // effective bias

#define SWZ128(o) ((o) ^ (((o) >> 3) & 0x70))

__device__ __forceinline__ uint32_t smem_u32(const void* p) {
    uint32_t a;
    asm("{ .reg .u64 t; cvta.to.shared.u64 t, %1; cvt.u32.u64 %0, t; }" : "=r"(a) : "l"(p));
    return a;
}

// ---- packed fp32x2 ----
__device__ __forceinline__ unsigned long long pack2(float a, float b) {
    unsigned long long r;
    asm("mov.b64 %0, {%1, %2};" : "=l"(r) : "f"(a), "f"(b));
    return r;
}
__device__ __forceinline__ void unpack2(unsigned long long p, float& a, float& b) {
    asm("mov.b64 {%0, %1}, %2;" : "=f"(a), "=f"(b) : "l"(p));
}
__device__ __forceinline__ unsigned long long fma2(unsigned long long a,
                                                   unsigned long long b,
                                                   unsigned long long c) {
    unsigned long long d;
    asm("fma.rn.f32x2 %0, %1, %2, %3;" : "=l"(d) : "l"(a), "l"(b), "l"(c));
    return d;
}

// ---- mma.sync / ldmatrix (plain sm_80+ PTX) ----
__device__ __forceinline__ void ldsm_x4(uint32_t addr, uint32_t* r) {
    asm volatile("ldmatrix.sync.aligned.m8n8.x4.shared.b16 {%0,%1,%2,%3}, [%4];"
        : "=r"(r[0]), "=r"(r[1]), "=r"(r[2]), "=r"(r[3]) : "r"(addr));
}
__device__ __forceinline__ void mma_bf16(float& d0, float& d1, float& d2, float& d3,
                                         uint4 a, uint32_t b0, uint32_t b1) {
    asm volatile("mma.sync.aligned.m16n8k16.row.col.f32.bf16.bf16.f32 "
        "{%0,%1,%2,%3}, {%4,%5,%6,%7}, {%8,%9}, {%0,%1,%2,%3};"
        : "+f"(d0), "+f"(d1), "+f"(d2), "+f"(d3)
        : "r"(a.x), "r"(a.y), "r"(a.z), "r"(a.w), "r"(b0), "r"(b1));
}

// ============================================================================
// k_prep: once per launch — W fragments (bf16 hi/lo, mma A-frag order),
//         Af = A+PA (padded), effective bias.  (verified)
// ============================================================================
__global__ __launch_bounds__(1024)
void k_prep(const float* __restrict__ W, const float* __restrict__ b,
            const float* __restrict__ A, const float* __restrict__ PA)
{
    __shared__ float saf[K_ * V_ * 28];
    __shared__ float scs[K_ * V_];
    const int tid = threadIdx.x;

    for (int idx = tid; idx < 6144; idx += 1024) {
        int j    = idx & 3;
        int lane = (idx >> 2) & 31;
        int mtks = idx >> 7;
        int mt = mtks >> 2, ks = mtks & 3;
        int g = lane >> 2, tg = lane & 3;
        int row = mt * 16 + g + ((j & 1) << 3);
        int col = ks * 16 + tg * 2 + ((j >> 1) << 3);
        float w0 = W[row * 64 + col], w1 = W[row * 64 + col + 1];
        __nv_bfloat16 h0 = __float2bfloat16(w0);
        __nv_bfloat16 h1 = __float2bfloat16(w1);
        __nv_bfloat16 l0 = __float2bfloat16(w0 - __bfloat162float(h0));
        __nv_bfloat16 l1 = __float2bfloat16(w1 - __bfloat162float(h1));
        uint32_t hw = (uint32_t)__bfloat16_as_ushort(h0) | ((uint32_t)__bfloat16_as_ushort(h1) << 16);
        uint32_t lw = (uint32_t)__bfloat16_as_ushort(l0) | ((uint32_t)__bfloat16_as_ushort(l1) << 16);
        g_wfrag[((mtks * 2 + 0) * 32 + lane) * 4 + j] = hw;
        g_wfrag[((mtks * 2 + 1) * 32 + lane) * 4 + j] = lw;
    }
    for (int i = tid; i < K_ * V_ * 28; i += 1024) {
        int kv = i / 28, w = i % 28;
        float v = (w < 25) ? (A[kv * 25 + w] + PA[kv * 25 + w]) : 0.f;
        saf[i] = v;
        g_af[i] = v;
    }
    __syncthreads();
    if (tid < 75) {
        int k = tid / 25, w = tid % 25;
        float s = 0.f;
        #pragma unroll
        for (int v = 0; v < 25; v++) s += saf[(k * 25 + v) * 28 + w];
        scs[tid] = s;
    }
    __syncthreads();
    for (int i = tid; i < C_ * V_; i += 1024) {
        int c = i / 25, w = i % 25;
        float s = 0.f;
        #pragma unroll
        for (int k = 0; k < 3; k++) s += b[k * 64 + c] * scs[k * 25 + w];
        g_beff[i] = s;
    }
}

// ============================================================================
// Pass 1: HMMA conv + agg in 2 rounds (half-Y) + stats; 3 CTAs/SM
// ============================================================================
__global__ __launch_bounds__(THREADS, 3)
void k_gcn(const float* __restrict__ x)
{
    extern __shared__ char smem[];
    const uint32_t sbase = smem_u32(smem);
    float* Ysm  = (float*)(smem + Y_B);
    float* Af   = (float*)(smem + AF_B);
    float* part = (float*)(smem + PART_B);

    const int tid = threadIdx.x;
    const int wid = tid >> 5;
    const int lid = tid & 31;

    const int bi = blockIdx.x;
    const int n  = bi >> 8;
    const int t0 = (bi & 255) * TPOS;

    // ---- setup: x -> bf16 hi/lo (cin-pairs packed), Af copy ----
    const float* xg = x + (size_t)n * (C_ * T_ * V_) + (size_t)t0 * V_;
    for (int i = tid; i < 3200; i += THREADS) {          // 32 cin-pairs x 100 r
        int cp = i / 100, r = i % 100;
        float xa = xg[(size_t)(2 * cp)     * (T_ * V_) + r];
        float xc = xg[(size_t)(2 * cp + 1) * (T_ * V_) + r];
        __nv_bfloat16 ha = __float2bfloat16(xa);
        __nv_bfloat16 hc = __float2bfloat16(xc);
        __nv_bfloat16 la = __float2bfloat16(xa - __bfloat162float(ha));
        __nv_bfloat16 lc = __float2bfloat16(xc - __bfloat162float(hc));
        uint32_t hw = (uint32_t)__bfloat16_as_ushort(ha) | ((uint32_t)__bfloat16_as_ushort(hc) << 16);
        uint32_t lw = (uint32_t)__bfloat16_as_ushort(la) | ((uint32_t)__bfloat16_as_ushort(lc) << 16);
        uint32_t off = SWZ128((uint32_t)(r * 128 + cp * 4));
        *(uint32_t*)(smem + XHI_B + off) = hw;
        *(uint32_t*)(smem + XLO_B + off) = lw;
    }
    for (int i = tid; i < 4 * 32; i += THREADS) {        // zero rows 100-103
        int r = 100 + (i >> 5), cp = i & 31;
        uint32_t off = SWZ128((uint32_t)(r * 128 + cp * 4));
        *(uint32_t*)(smem + XHI_B + off) = 0u;
        *(uint32_t*)(smem + XLO_B + off) = 0u;
    }
    for (int i = tid; i < K_ * V_ * 28; i += THREADS) Af[i] = g_af[i];
    __syncthreads();

    float s1 = 0.f, s2 = 0.f;

    #pragma unroll 1
    for (int round = 0; round < 2; round++) {
        // ---- MMA round: nt in [6*round, 6*round+6], store Y cols round*50..+49
        {
            const uint4* wf4 = (const uint4*)g_wfrag;
            for (int mt = wid; mt < 12; mt += 8) {
                uint4 fh[4], fl[4];
                #pragma unroll
                for (int ks = 0; ks < 4; ks++) {
                    fh[ks] = wf4[((mt * 4 + ks) * 2 + 0) * 32 + lid];
                    fl[ks] = wf4[((mt * 4 + ks) * 2 + 1) * 32 + lid];
                }
                for (int nt = round * 6; nt <= round * 6 + 6; nt++) {
                    uint32_t bh[8], bl[8];
                    #pragma unroll
                    for (int k2 = 0; k2 < 2; k2++) {
                        uint32_t off = SWZ128((uint32_t)((nt * 8 + (lid & 7)) * 128
                                        + k2 * 64 + (lid >> 3) * 16));
                        ldsm_x4(sbase + XHI_B + off, bh + k2 * 4);
                        ldsm_x4(sbase + XLO_B + off, bl + k2 * 4);
                    }
                    float hh0=0,hh1=0,hh2=0,hh3=0, lh0=0,lh1=0,lh2=0,lh3=0, hl0=0,hl1=0,hl2=0,hl3=0;
                    #pragma unroll
                    for (int ks = 0; ks < 4; ks++) {
                        uint32_t b0 = bh[ks * 2], b1 = bh[ks * 2 + 1];
                        mma_bf16(hh0, hh1, hh2, hh3, fh[ks], b0, b1);
                        mma_bf16(lh0, lh1, lh2, lh3, fl[ks], b0, b1);
                        mma_bf16(hl0, hl1, hl2, hl3, fh[ks], bl[ks * 2], bl[ks * 2 + 1]);
                    }
                    const int r0 = mt * 16 + (lid >> 2);
                    const int c0 = nt * 8 + (lid & 3) * 2;
                    const int cl = c0 - round * 50;
                    if (cl >= 0 && cl < 50) {
                        Ysm[r0 * 51 + cl]           = hh0 + lh0 + hl0;
                        Ysm[r0 * 51 + cl + 1]       = hh1 + lh1 + hl1;
                        Ysm[(r0 + 8) * 51 + cl]     = hh2 + lh2 + hl2;
                        Ysm[(r0 + 8) * 51 + cl + 1] = hh3 + lh3 + hl3;
                    }
                }
            }
        }
        __syncthreads();

        // ---- agg round: thread owns (c, pr, w-half); direct coalesced STG ----
        {
            const int c  = tid & 63;
            const int pr = (tid >> 6) & 1;
            const int h  = tid >> 7;
            const int w0 = h * 12;

            unsigned long long acc[6];
            float acc24 = 0.f;
            {
                const float* bec = g_beff + c * 25 + w0;
                #pragma unroll
                for (int j = 0; j < 6; j++) acc[j] = pack2(__ldg(bec + 2 * j), __ldg(bec + 2 * j + 1));
                if (h) acc24 = __ldg(&g_beff[c * 25 + 24]);
            }

            #pragma unroll 1
            for (int k = 0; k < 3; k++) {
                const float* yrow = Ysm + (k * 64 + c) * 51 + pr * 25;   // stride 51: conflict-free
                const float* afk  = Af + k * 25 * 28 + w0;
                #pragma unroll 5
                for (int v = 0; v < 25; v++) {
                    float yv = yrow[v];
                    unsigned long long yp = pack2(yv, yv);
                    const ulonglong2* a2 = (const ulonglong2*)(afk + v * 28);  // 16B-aligned
                    ulonglong2 aa0 = a2[0];
                    acc[0] = fma2(yp, aa0.x, acc[0]);
                    acc[1] = fma2(yp, aa0.y, acc[1]);
                    unsigned long long aa2 = *(const unsigned long long*)(afk + v * 28 + 4);
                    unsigned long long aa3 = *(const unsigned long long*)(afk + v * 28 + 6);
                    acc[2] = fma2(yp, aa2, acc[2]);
                    acc[3] = fma2(yp, aa3, acc[3]);
                    unsigned long long aa4 = *(const unsigned long long*)(afk + v * 28 + 8);
                    unsigned long long aa5 = *(const unsigned long long*)(afk + v * 28 + 10);
                    acc[4] = fma2(yp, aa4, acc[4]);
                    acc[5] = fma2(yp, aa5, acc[5]);
                    if (h) acc24 = fmaf(yv, Af[(k * 25 + v) * 28 + 24], acc24);
                }
            }

            float vals[13];
            #pragma unroll
            for (int j = 0; j < 6; j++) unpack2(acc[j], vals[2 * j], vals[2 * j + 1]);
            vals[12] = acc24;
            const int nv = h ? 13 : 12;

            #pragma unroll
            for (int j = 0; j < 13; j++)
                if (j < nv) { float a = vals[j]; s1 += a; s2 += a * a; }

            // transposed layout [n][t][v][c]: lanes (consecutive c) coalesce per j
            float* gp = g_agg2 + (((size_t)(n * 1024 + t0 + round * 2 + pr)) * 25 + w0) * 64 + c;
            #pragma unroll
            for (int j = 0; j < 13; j++)
                if (j < nv) gp[j * 64] = vals[j];
        }
        __syncthreads();     // protect Y before next MMA round
    }

    // ---- stats: deterministic partial reduce ----
    part[tid] = s1;
    part[256 + tid] = s2;
    __syncthreads();
    if (tid < 64) {
        float p1 = part[tid] + part[64 + tid] + part[128 + tid] + part[192 + tid];
        float p2 = part[256 + tid] + part[320 + tid] + part[384 + tid] + part[448 + tid];
        g_psum[bi * 64 + tid]   = p1;
        g_psumsq[bi * 64 + tid] = p2;
    }
}

// ============================================================================
// Pass 2: reduce partials -> per-channel scale/shift
// ============================================================================
__global__ void k_stats(const float* __restrict__ gamma, const float* __restrict__ beta)
{
    const int ch = blockIdx.x;
    const int tid = threadIdx.x;
    __shared__ float s1s[256], s2s[256];
    float s1 = 0.f, s2 = 0.f;
    for (int j = tid; j < NBLK1; j += 256) {
        s1 += g_psum[j * 64 + ch];
        s2 += g_psumsq[j * 64 + ch];
    }
    s1s[tid] = s1; s2s[tid] = s2;
    __syncthreads();
    for (int st = 128; st > 0; st >>= 1) {
        if (tid < st) { s1s[tid] += s1s[tid + st]; s2s[tid] += s2s[tid + st]; }
        __syncthreads();
    }
    if (tid == 0) {
        const float cnt = (float)N_ * T_ * V_;
        float mu   = s1s[0] / cnt;
        float var  = s2s[0] / cnt - mu * mu;
        float rstd = rsqrtf(var + EPSV);
        float sc   = gamma[ch] * rstd;
        g_scale[ch] = sc;
        g_shift[ch] = beta[ch] - mu * sc;
    }
}

// ============================================================================
// Pass 3: tiled transpose + BN + relu + residual.
// Block = (n, 8 t). Load agg2 [200 f][64 c] coalesced -> smem stride-65 ->
// emit in [c][f] order (coalesced x/out).
// ============================================================================
__global__ __launch_bounds__(256, 4)
void k_out(const float* __restrict__ x, float* __restrict__ out)
{
    extern __shared__ float sm[];     // [200][65]
    const int tid = threadIdx.x;
    const int bi  = blockIdx.x;
    const int n   = bi >> 7;          // 128 t-tiles per n
    const int tb  = (bi & 127) * 8;   // t base

    const float* src = g_agg2 + ((size_t)(n * 1024 + tb)) * 25 * 64;
    for (int i = tid; i < 12800; i += 256) {
        int f = i >> 6, c = i & 63;
        sm[f * 65 + c] = src[i];      // lanes: consecutive c -> coalesced LDG + conflict-free STS
    }
    __syncthreads();

    for (int i = tid; i < 12800; i += 256) {
        int c = i / 200, f = i % 200;
        size_t g = (size_t)(n * 64 + c) * 25600 + (size_t)tb * 25 + f;
        float sc = g_scale[c], sh = g_shift[c];
        float a = sm[f * 65 + c];     // lanes: consecutive f, stride 65 -> conflict-free
        out[g] = fmaxf(fmaf(a, sc, sh) + x[g], 0.f);
    }
}

// ============================================================================
extern "C" void kernel_launch(void* const* d_in, const int* in_sizes, int n_in,
                              void* d_out, int out_size)
{
    const float* x     = (const float*)d_in[0];
    const float* W     = (const float*)d_in[1];
    const float* b     = (const float*)d_in[2];
    const float* A     = (const float*)d_in[3];
    const float* PA    = (const float*)d_in[4];
    const float* gamma = (const float*)d_in[5];
    const float* beta  = (const float*)d_in[6];
    float* out = (float*)d_out;

    cudaFuncSetAttribute(k_gcn, cudaFuncAttributeMaxDynamicSharedMemorySize, SMEM_TOTAL);
    cudaFuncSetAttribute(k_out, cudaFuncAttributeMaxDynamicSharedMemorySize, KOUT_SMEM);

    k_prep<<<1, 1024>>>(W, b, A, PA);
    k_gcn<<<NBLK1, THREADS, SMEM_TOTAL>>>(x);
    k_stats<<<C_, 256>>>(gamma, beta);
    k_out<<<N_ * 128, 256, KOUT_SMEM>>>(x, out);
}